// round 2
// baseline (speedup 1.0000x reference)
#include <cuda_runtime.h>
#include <cstdint>

// MaxUnpooling2D: out[b, y, x, f] += updates[b,h,w,f] where (y,x) decoded from
// mask (flattened [outH,outW,C] index; channel bits of mask are DISCARDED and
// replaced by the element's own channel f = i % C).
//
// Shapes: updates [32,112,112,64] f32, mask int32 same, out [32,224,224,64] f32.
// out_idx = b*outHWC + (m & ~(C-1)) + (i & (C-1))   (C = 64, power of two)

static constexpr int C_ = 64;
static constexpr int IN_HWC = 112 * 112 * 64;          // 802,816 per batch
static constexpr long long OUT_HWC = 224LL * 224 * 64; // 3,211,264 per batch

// ---------------- zero fill (vectorized) ----------------
__global__ void zero_kernel(float4* __restrict__ out, long long n4) {
    long long i = (long long)blockIdx.x * blockDim.x + threadIdx.x;
    if (i < n4) out[i] = make_float4(0.f, 0.f, 0.f, 0.f);
}

// ---------------- scatter-add ----------------
// One thread handles 4 consecutive elements (same row, consecutive channels).
// blockIdx maps LINEARLY onto the input so that the in-flight CTA wave covers
// a narrow batch window -> atomic footprint stays L2-resident.
__global__ void scatter_kernel(const float4* __restrict__ upd4,
                               const int4* __restrict__ msk4,
                               float* __restrict__ out,
                               int n4) {
    int i4 = blockIdx.x * blockDim.x + threadIdx.x;
    if (i4 >= n4) return;

    float4 u = upd4[i4];
    int4 m = msk4[i4];

    unsigned i = (unsigned)i4 * 4u;        // element index (fits 32-bit)
    unsigned b = i / (unsigned)IN_HWC;     // batch (32-bit div)
    unsigned c = i & (C_ - 1);             // channel of first element
    float* outb = out + (long long)b * OUT_HWC;

    // out offset: clear channel bits of mask, add our own channel
    atomicAdd(outb + (((unsigned)m.x & ~(unsigned)(C_ - 1)) + c + 0u), u.x);
    atomicAdd(outb + (((unsigned)m.y & ~(unsigned)(C_ - 1)) + c + 1u), u.y);
    atomicAdd(outb + (((unsigned)m.z & ~(unsigned)(C_ - 1)) + c + 2u), u.z);
    atomicAdd(outb + (((unsigned)m.w & ~(unsigned)(C_ - 1)) + c + 3u), u.w);
}

extern "C" void kernel_launch(void* const* d_in, const int* in_sizes, int n_in,
                              void* d_out, int out_size) {
    const float* updates = (const float*)d_in[0];
    const int* mask = (const int*)d_in[1];
    float* out = (float*)d_out;

    long long n = (long long)in_sizes[0];     // 25,690,112
    int n4 = (int)(n / 4);                    // 6,422,528
    long long o4 = (long long)out_size / 4;   // 25,690,112

    {
        int threads = 256;
        long long blocks = (o4 + threads - 1) / threads;
        zero_kernel<<<(unsigned)blocks, threads>>>((float4*)out, o4);
    }
    {
        int threads = 256;
        int blocks = (n4 + threads - 1) / threads;
        scatter_kernel<<<blocks, threads>>>(
            (const float4*)updates, (const int4*)mask, out, n4);
    }
}

// round 4
// speedup vs baseline: 1.5668x; 1.5668x over previous
#include <cuda_runtime.h>
#include <cstdint>

// MaxUnpooling2D scatter-add, chunk-interleaved for L2 residency.
//
// out_idx = b*OUT_HWC + (mask & ~(C-1)) + (i & (C-1)),  C = 64.
// updates [32,112,112,64] f32, mask int32 same shape, out [32,224,224,64] f32.
//
// Key optimization vs R2: interleave zero(chunk) -> scatter(chunk) per 4-batch
// chunk (51.4 MB output window << 126 MB L2). The zero's dirty lines are still
// L2-resident when the scatter's REDG ops hit them, so atomics are pure L2 RMW
// and each output byte costs exactly one DRAM writeback (evicted by the next
// chunk's zero). DRAM traffic: 1.44 GB -> ~617 MB.

static constexpr int C_ = 64;
static constexpr int IN_HWC = 112 * 112 * 64;          // 802,816  per batch
static constexpr int OUT_HWC = 224 * 224 * 64;         // 3,211,264 per batch
static constexpr int NB = 32;                          // batches
static constexpr int CHUNK_B = 4;                      // batches per chunk
static constexpr int NCHUNK = NB / CHUNK_B;            // 8 chunks

// ---------------- zero fill (one chunk) ----------------
__global__ void zero_chunk_kernel(float4* __restrict__ out4, int n4) {
    int i = blockIdx.x * blockDim.x + threadIdx.x;
    if (i < n4) out4[i] = make_float4(0.f, 0.f, 0.f, 0.f);
}

// ---------------- scatter-add (one chunk) ----------------
// One thread = 4 consecutive elements (same row, consecutive channels).
// Linear block->input mapping keeps the in-flight atomic window narrow.
__global__ void scatter_chunk_kernel(const float4* __restrict__ upd4,
                                     const int4* __restrict__ msk4,
                                     float* __restrict__ outb_base, // out + chunk_b0*OUT_HWC
                                     int n4) {
    int i4 = blockIdx.x * blockDim.x + threadIdx.x;
    if (i4 >= n4) return;

    float4 u = upd4[i4];
    int4 m = msk4[i4];

    unsigned i = (unsigned)i4 * 4u;             // element index within chunk
    unsigned brel = i / (unsigned)IN_HWC;       // batch within chunk (0..3)
    unsigned c = i & (C_ - 1);                  // first channel
    float* outb = outb_base + (long long)brel * OUT_HWC;

    atomicAdd(outb + (((unsigned)m.x & ~(unsigned)(C_ - 1)) + c + 0u), u.x);
    atomicAdd(outb + (((unsigned)m.y & ~(unsigned)(C_ - 1)) + c + 1u), u.y);
    atomicAdd(outb + (((unsigned)m.z & ~(unsigned)(C_ - 1)) + c + 2u), u.z);
    atomicAdd(outb + (((unsigned)m.w & ~(unsigned)(C_ - 1)) + c + 3u), u.w);
}

extern "C" void kernel_launch(void* const* d_in, const int* in_sizes, int n_in,
                              void* d_out, int out_size) {
    const float* updates = (const float*)d_in[0];
    const int* mask = (const int*)d_in[1];
    float* out = (float*)d_out;

    const int in_chunk_elems = CHUNK_B * IN_HWC;        // 3,211,264
    const int in_chunk_n4 = in_chunk_elems / 4;         // 802,816
    const int out_chunk_elems = CHUNK_B * OUT_HWC;      // 12,845,056
    const int out_chunk_n4 = out_chunk_elems / 4;       // 3,211,264

    const int threads = 256;
    const int zblocks = (out_chunk_n4 + threads - 1) / threads;
    const int sblocks = (in_chunk_n4 + threads - 1) / threads;

    for (int k = 0; k < NCHUNK; k++) {
        const long long in_off = (long long)k * in_chunk_elems;
        const long long out_off = (long long)k * out_chunk_elems;

        // Zero this chunk's output window (leaves dirty lines in L2)...
        zero_chunk_kernel<<<zblocks, threads>>>(
            (float4*)(out + out_off), out_chunk_n4);

        // ...then immediately scatter into it while it is L2-resident.
        scatter_chunk_kernel<<<sblocks, threads>>>(
            (const float4*)(updates + in_off),
            (const int4*)(mask + in_off),
            out + out_off,
            in_chunk_n4);
    }
}